// round 3
// baseline (speedup 1.0000x reference)
#include <cuda_runtime.h>

#define HH 1024
#define WW 1024
#define NPIX (HH * WW)
#define NB 8

// Ping-pong scratch: [ping][x_or_y][image*NPIX]
__device__ float  g_buf[2][2][NB * NPIX];
__device__ float  g_part[5][256];
__device__ double g_term[NB];

// ---------------------------------------------------------------------------
// Kernel 1: channel sum  S[b] = x[b,0]+x[b,1]+x[b,2]  (and same for y)
// ---------------------------------------------------------------------------
__global__ void sum_ch_kernel(const float4* __restrict__ x,
                              const float4* __restrict__ y) {
    const int n4 = NPIX / 4;
    int i = blockIdx.x * blockDim.x + threadIdx.x;
    if (i >= NB * n4) return;
    int img = i / n4;
    int p   = i - img * n4;

    const float4* xs = x + (size_t)img * 3 * n4;
    float4 a = xs[p], b = xs[p + n4], c = xs[p + 2 * n4];
    ((float4*)g_buf[0][0])[i] =
        make_float4(a.x + b.x + c.x, a.y + b.y + c.y,
                    a.z + b.z + c.z, a.w + b.w + c.w);

    const float4* ys = y + (size_t)img * 3 * n4;
    a = ys[p]; b = ys[p + n4]; c = ys[p + 2 * n4];
    ((float4*)g_buf[0][1])[i] =
        make_float4(a.x + b.x + c.x, a.y + b.y + c.y,
                    a.z + b.z + c.z, a.w + b.w + c.w);
}

// ---------------------------------------------------------------------------
// Kernel 2: 3x3 zero-padded conv, smem-tiled. Tile = 128x8 outputs/block.
// blockIdx.z enumerates (x planes for img t..7) then (y planes for img t..7).
// ---------------------------------------------------------------------------
__global__ void conv_kernel(int srcp, int t) {
    const int nimg = NB - t;
    int z  = blockIdx.z;
    int xy = (z >= nimg) ? 1 : 0;
    int img = t + z - xy * nimg;
    const float* __restrict__ src = g_buf[srcp][xy]     + (size_t)img * NPIX;
    float*       __restrict__ dst = g_buf[srcp ^ 1][xy] + (size_t)img * NPIX;

    __shared__ float s[10][132];
    const int x0 = blockIdx.x * 128;
    const int y0 = blockIdx.y * 8;
    const int tid = threadIdx.y * 32 + threadIdx.x;

    // Load (128+2) x (8+2) halo tile with zero fill at image boundary
    for (int i = tid; i < 10 * 130; i += 256) {
        int r = i / 130, c = i - r * 130;
        int gy = y0 - 1 + r, gx = x0 - 1 + c;
        float v = 0.0f;
        if ((unsigned)gy < HH && (unsigned)gx < WW) v = src[gy * WW + gx];
        s[r][c] = v;
    }
    __syncthreads();

    const float KA = 0.03797616f;   // corners
    const float KB = 0.044863533f;  // edges
    const float KC = 0.053f;        // center
    const int ty = threadIdx.y;
    const int cx = threadIdx.x * 4 + 1;

    float o[4];
#pragma unroll
    for (int j = 0; j < 4; j++) {
        int cc = cx + j;
        o[j] = KA * (s[ty][cc - 1] + s[ty][cc + 1] + s[ty + 2][cc - 1] + s[ty + 2][cc + 1])
             + KB * (s[ty][cc] + s[ty + 2][cc] + s[ty + 1][cc - 1] + s[ty + 1][cc + 1])
             + KC * s[ty + 1][cc];
    }
    *(float4*)(dst + (size_t)(y0 + ty) * WW + x0 + threadIdx.x * 4) =
        make_float4(o[0], o[1], o[2], o[3]);
}

// ---------------------------------------------------------------------------
// Kernel 3: 5-moment reduction over image t (u = conv^(t+1) Sx, v = same for y)
// ---------------------------------------------------------------------------
__inline__ __device__ float warpSumF(float v) {
#pragma unroll
    for (int o = 16; o; o >>= 1) v += __shfl_down_sync(0xffffffffu, v, o);
    return v;
}

__global__ void stats_kernel(int ping, int t) {
    const float4* __restrict__ u = (const float4*)(g_buf[ping][0] + (size_t)t * NPIX);
    const float4* __restrict__ v = (const float4*)(g_buf[ping][1] + (size_t)t * NPIX);
    float su = 0, su2 = 0, sv = 0, sv2 = 0, suv = 0;
    const int n4 = NPIX / 4;
    for (int i = blockIdx.x * blockDim.x + threadIdx.x; i < n4;
         i += gridDim.x * blockDim.x) {
        float4 a = u[i], b = v[i];
        su  += a.x + a.y + a.z + a.w;
        su2 += a.x * a.x + a.y * a.y + a.z * a.z + a.w * a.w;
        sv  += b.x + b.y + b.z + b.w;
        sv2 += b.x * b.x + b.y * b.y + b.z * b.z + b.w * b.w;
        suv += a.x * b.x + a.y * b.y + a.z * b.z + a.w * b.w;
    }
    su = warpSumF(su); su2 = warpSumF(su2); sv = warpSumF(sv);
    sv2 = warpSumF(sv2); suv = warpSumF(suv);

    __shared__ float sm[5][8];
    int lane = threadIdx.x & 31, w = threadIdx.x >> 5;
    if (lane == 0) {
        sm[0][w] = su; sm[1][w] = su2; sm[2][w] = sv;
        sm[3][w] = sv2; sm[4][w] = suv;
    }
    __syncthreads();
    if (threadIdx.x == 0) {
#pragma unroll
        for (int k = 0; k < 5; k++) {
            float r = 0.0f;
#pragma unroll
            for (int q = 0; q < 8; q++) r += sm[k][q];
            g_part[k][blockIdx.x] = r;
        }
    }
}

// ---------------------------------------------------------------------------
// Kernel 4: finalize one SSIM term (double precision)
// ---------------------------------------------------------------------------
__inline__ __device__ double warpSumD(double v) {
#pragma unroll
    for (int o = 16; o; o >>= 1) v += __shfl_down_sync(0xffffffffu, v, o);
    return v;
}

__global__ void finalize_kernel(int t) {
    double a0 = (double)g_part[0][threadIdx.x];
    double a1 = (double)g_part[1][threadIdx.x];
    double a2 = (double)g_part[2][threadIdx.x];
    double a3 = (double)g_part[3][threadIdx.x];
    double a4 = (double)g_part[4][threadIdx.x];
    a0 = warpSumD(a0); a1 = warpSumD(a1); a2 = warpSumD(a2);
    a3 = warpSumD(a3); a4 = warpSumD(a4);

    __shared__ double sm[5][8];
    int lane = threadIdx.x & 31, w = threadIdx.x >> 5;
    if (lane == 0) {
        sm[0][w] = a0; sm[1][w] = a1; sm[2][w] = a2;
        sm[3][w] = a3; sm[4][w] = a4;
    }
    __syncthreads();
    if (threadIdx.x == 0) {
        double SU = 0, SU2 = 0, SV = 0, SV2 = 0, SUV = 0;
#pragma unroll
        for (int q = 0; q < 8; q++) {
            SU += sm[0][q]; SU2 += sm[1][q]; SV += sm[2][q];
            SV2 += sm[3][q]; SUV += sm[4][q];
        }
        double sc = 1.0;
        for (int i = 0; i < t; i++) sc *= 3.0;  // 3^t channel-mixing gain
        const double N = (double)NPIX;
        const double C1 = 6.5025;    // (0.01*255)^2
        const double C2 = 58.5225;   // (0.03*255)^2
        double mu = sc * SU / N;
        double mv = sc * SV / N;
        double varu = sc * sc * (SU2 - SU * SU / N) / (N - 1.0);
        double varv = sc * sc * (SV2 - SV * SV / N) / (N - 1.0);
        double cov  = sc * sc * (SUV - SU * SV / N) / (N - 1.0);
        g_term[t] = ((2.0 * mu * mv + C1) * (2.0 * cov + C2)) /
                    ((mu * mu + mv * mv + C1) * (varu * varu + varv * varv + C2));
    }
}

__global__ void sum8_kernel(float* __restrict__ out) {
    double s = 0.0;
#pragma unroll
    for (int i = 0; i < NB; i++) s += g_term[i];
    out[0] = (float)s;
}

// ---------------------------------------------------------------------------
extern "C" void kernel_launch(void* const* d_in, const int* in_sizes, int n_in,
                              void* d_out, int out_size) {
    const float4* x = (const float4*)d_in[0];
    const float4* y = (const float4*)d_in[1];
    float* out = (float*)d_out;

    // 1) channel sums into ping 0
    sum_ch_kernel<<<(NB * NPIX / 4 + 255) / 256, 256>>>(x, y);

    // 2) 8 iterations: conv images [t,8) for both inputs, then stats on image t
    for (int t = 0; t < NB; t++) {
        dim3 grid(WW / 128, HH / 8, 2 * (NB - t));
        conv_kernel<<<grid, dim3(32, 8)>>>(t & 1, t);
        stats_kernel<<<256, 256>>>((t & 1) ^ 1, t);
        finalize_kernel<<<1, 256>>>(t);
    }

    // 3) sum the 8 terms
    sum8_kernel<<<1, 1>>>(out);
}

// round 4
// speedup vs baseline: 1.2760x; 1.2760x over previous
#include <cuda_runtime.h>

#define HH 1024
#define WW 1024
#define NPIX (HH * WW)
#define NB 8
#define NBLK 1024  // (1024/128) x (1024/8) blocks per plane

// Ping-pong scratch planes and per-block moment partials
__device__ float g_buf[2][2][NB * NPIX];
__device__ float g_part[NB][5][NBLK];  // [t][moment][block], moment: su,su2,sv,sv2,suv

#define KA 0.03797616f
#define KB 0.044863533f
#define KC 0.053f

__inline__ __device__ float warpSumF(float v) {
#pragma unroll
    for (int o = 16; o; o >>= 1) v += __shfl_down_sync(0xffffffffu, v, o);
    return v;
}
__inline__ __device__ double warpSumD(double v) {
#pragma unroll
    for (int o = 16; o; o >>= 1) v += __shfl_down_sync(0xffffffffu, v, o);
    return v;
}

// ---------------------------------------------------------------------------
// Conv step t. grid = (8, 128, 1 + 2*(NB-t-1)), block = (32, 8).
//   z == 0 : FUSED block — conv x-plane AND y-plane of image t, compute the 5
//            moment partials, write NO plane output (image t is dead after this).
//   z >= 1 : plain conv of image t+1+q (q = z-1), x planes first then y.
// FROM_INPUT: read the 3 raw input channels and sum on the fly (t == 0 only).
// ---------------------------------------------------------------------------
template <bool FROM_INPUT>
__global__ void conv_kernel(const float* __restrict__ xin,
                            const float* __restrict__ yin, int t) {
    __shared__ float sx[10][132];
    __shared__ float sy[10][132];

    const int nimg = NB - t;
    const int z = blockIdx.z;
    const int x0 = blockIdx.x * 128;
    const int y0 = blockIdx.y * 8;
    const int tid = threadIdx.y * 32 + threadIdx.x;
    const int ty = threadIdx.y;
    const int srcp = t & 1;

    if (z == 0) {
        // ---- fused stats block for image t (both x and y planes) ----
        const float* __restrict__ sxp;
        const float* __restrict__ syp;
        if (FROM_INPUT) {
            sxp = xin + (size_t)t * 3 * NPIX;
            syp = yin + (size_t)t * 3 * NPIX;
        } else {
            sxp = g_buf[srcp][0] + (size_t)t * NPIX;
            syp = g_buf[srcp][1] + (size_t)t * NPIX;
        }
        for (int i = tid; i < 10 * 130; i += 256) {
            int r = i / 130, c = i - r * 130;
            int gy = y0 - 1 + r, gx = x0 - 1 + c;
            float vx = 0.0f, vy = 0.0f;
            if ((unsigned)gy < HH && (unsigned)gx < WW) {
                size_t o = (size_t)gy * WW + gx;
                if (FROM_INPUT) {
                    vx = sxp[o] + sxp[o + NPIX] + sxp[o + 2 * NPIX];
                    vy = syp[o] + syp[o + NPIX] + syp[o + 2 * NPIX];
                } else {
                    vx = sxp[o];
                    vy = syp[o];
                }
            }
            sx[r][c] = vx;
            sy[r][c] = vy;
        }
        __syncthreads();

        float su = 0, su2 = 0, sv = 0, sv2 = 0, suv = 0;
#pragma unroll
        for (int j = 0; j < 4; j++) {
            int cc = threadIdx.x * 4 + 1 + j;
            float ox = KA * (sx[ty][cc - 1] + sx[ty][cc + 1] + sx[ty + 2][cc - 1] + sx[ty + 2][cc + 1])
                     + KB * (sx[ty][cc] + sx[ty + 2][cc] + sx[ty + 1][cc - 1] + sx[ty + 1][cc + 1])
                     + KC * sx[ty + 1][cc];
            float oy = KA * (sy[ty][cc - 1] + sy[ty][cc + 1] + sy[ty + 2][cc - 1] + sy[ty + 2][cc + 1])
                     + KB * (sy[ty][cc] + sy[ty + 2][cc] + sy[ty + 1][cc - 1] + sy[ty + 1][cc + 1])
                     + KC * sy[ty + 1][cc];
            su += ox; su2 += ox * ox;
            sv += oy; sv2 += oy * oy;
            suv += ox * oy;
        }
        su = warpSumF(su); su2 = warpSumF(su2); sv = warpSumF(sv);
        sv2 = warpSumF(sv2); suv = warpSumF(suv);

        __shared__ float red[5][8];
        int lane = threadIdx.x & 31;
        if (lane == 0) {
            red[0][ty] = su; red[1][ty] = su2; red[2][ty] = sv;
            red[3][ty] = sv2; red[4][ty] = suv;
        }
        __syncthreads();
        if (tid < 5) {
            float r = 0.0f;
#pragma unroll
            for (int q = 0; q < 8; q++) r += red[tid][q];
            g_part[t][tid][blockIdx.y * gridDim.x + blockIdx.x] = r;
        }
    } else {
        // ---- plain conv of a future image ----
        int q = z - 1;
        int xy = (q >= nimg - 1) ? 1 : 0;
        int img = t + 1 + q - xy * (nimg - 1);
        const float* __restrict__ src;
        if (FROM_INPUT)
            src = (xy ? yin : xin) + (size_t)img * 3 * NPIX;
        else
            src = g_buf[srcp][xy] + (size_t)img * NPIX;
        float* __restrict__ dst = g_buf[srcp ^ 1][xy] + (size_t)img * NPIX;

        for (int i = tid; i < 10 * 130; i += 256) {
            int r = i / 130, c = i - r * 130;
            int gy = y0 - 1 + r, gx = x0 - 1 + c;
            float v = 0.0f;
            if ((unsigned)gy < HH && (unsigned)gx < WW) {
                size_t o = (size_t)gy * WW + gx;
                if (FROM_INPUT)
                    v = src[o] + src[o + NPIX] + src[o + 2 * NPIX];
                else
                    v = src[o];
            }
            sx[r][c] = v;
        }
        __syncthreads();

        float o4[4];
#pragma unroll
        for (int j = 0; j < 4; j++) {
            int cc = threadIdx.x * 4 + 1 + j;
            o4[j] = KA * (sx[ty][cc - 1] + sx[ty][cc + 1] + sx[ty + 2][cc - 1] + sx[ty + 2][cc + 1])
                  + KB * (sx[ty][cc] + sx[ty + 2][cc] + sx[ty + 1][cc - 1] + sx[ty + 1][cc + 1])
                  + KC * sx[ty + 1][cc];
        }
        *(float4*)(dst + (size_t)(y0 + ty) * WW + x0 + threadIdx.x * 4) =
            make_float4(o4[0], o4[1], o4[2], o4[3]);
    }
}

// ---------------------------------------------------------------------------
// Tail: reduce all partials, compute the 8 SSIM terms in double, sum, write.
// One block, 256 threads; warp m (m<5) reduces moment m over the 1024 blocks.
// ---------------------------------------------------------------------------
__global__ void final_kernel(float* __restrict__ out) {
    const int w = threadIdx.x >> 5;
    const int lane = threadIdx.x & 31;
    __shared__ double sm[5];
    __shared__ double total_s;
    if (threadIdx.x == 0) total_s = 0.0;

    for (int t = 0; t < NB; t++) {
        if (w < 5) {
            double s = 0.0;
            for (int b = lane; b < NBLK; b += 32)
                s += (double)g_part[t][w][b];
            s = warpSumD(s);
            if (lane == 0) sm[w] = s;
        }
        __syncthreads();
        if (threadIdx.x == 0) {
            double SU = sm[0], SU2 = sm[1], SV = sm[2], SV2 = sm[3], SUV = sm[4];
            double sc = 1.0;
            for (int i = 0; i < t; i++) sc *= 3.0;  // 3^t channel-mixing gain
            const double N = (double)NPIX;
            const double C1 = 6.5025;   // (0.01*255)^2
            const double C2 = 58.5225;  // (0.03*255)^2
            double mu = sc * SU / N;
            double mv = sc * SV / N;
            double varu = sc * sc * (SU2 - SU * SU / N) / (N - 1.0);
            double varv = sc * sc * (SV2 - SV * SV / N) / (N - 1.0);
            double cov  = sc * sc * (SUV - SU * SV / N) / (N - 1.0);
            total_s += ((2.0 * mu * mv + C1) * (2.0 * cov + C2)) /
                       ((mu * mu + mv * mv + C1) * (varu * varu + varv * varv + C2));
        }
        __syncthreads();
    }
    if (threadIdx.x == 0) out[0] = (float)total_s;
}

// ---------------------------------------------------------------------------
extern "C" void kernel_launch(void* const* d_in, const int* in_sizes, int n_in,
                              void* d_out, int out_size) {
    const float* x = (const float*)d_in[0];
    const float* y = (const float*)d_in[1];
    float* out = (float*)d_out;

    for (int t = 0; t < NB; t++) {
        dim3 grid(WW / 128, HH / 8, 1 + 2 * (NB - t - 1));
        dim3 blk(32, 8);
        if (t == 0)
            conv_kernel<true><<<grid, blk>>>(x, y, t);
        else
            conv_kernel<false><<<grid, blk>>>(x, y, t);
    }
    final_kernel<<<1, 256>>>(out);
}

// round 5
// speedup vs baseline: 1.4948x; 1.1714x over previous
#include <cuda_runtime.h>

#define HH 1024
#define WW 1024
#define NPIX (HH * WW)
#define NB 8
#define NBLK 1024  // (1024/128) x (1024/8) blocks per plane

// Ping-pong scratch planes and per-block moment partials
__device__ float g_buf[2][2][NB * NPIX];
__device__ float g_part[NB][5][NBLK];  // [t][moment][block]: su,su2,sv,sv2,suv

#define KA 0.03797616f
#define KB 0.044863533f
#define KC 0.053f

__inline__ __device__ float warpSumF(float v) {
#pragma unroll
    for (int o = 16; o; o >>= 1) v += __shfl_down_sync(0xffffffffu, v, o);
    return v;
}
__inline__ __device__ double warpSumD(double v) {
#pragma unroll
    for (int o = 16; o; o >>= 1) v += __shfl_down_sync(0xffffffffu, v, o);
    return v;
}

__device__ __forceinline__ float c3(const float (*s)[136], int r, int c) {
    return KA * (s[r - 1][c - 1] + s[r - 1][c + 1] + s[r + 1][c - 1] + s[r + 1][c + 1])
         + KB * (s[r - 1][c] + s[r + 1][c] + s[r][c - 1] + s[r][c + 1])
         + KC * s[r][c];
}

// ---------------------------------------------------------------------------
// Block-wide 5-moment reduction and partial write.
// ---------------------------------------------------------------------------
__device__ __forceinline__ void emit_stats(float su, float su2, float sv,
                                           float sv2, float suv, int t) {
    su = warpSumF(su); su2 = warpSumF(su2); sv = warpSumF(sv);
    sv2 = warpSumF(sv2); suv = warpSumF(suv);
    __shared__ float red[5][8];
    const int lane = threadIdx.x & 31;
    const int w = threadIdx.y;
    if (lane == 0) {
        red[0][w] = su; red[1][w] = su2; red[2][w] = sv;
        red[3][w] = sv2; red[4][w] = suv;
    }
    __syncthreads();
    const int tid = threadIdx.y * 32 + threadIdx.x;
    if (tid < 5) {
        float r = 0.0f;
#pragma unroll
        for (int q = 0; q < 8; q++) r += red[tid][q];
        g_part[t][tid][blockIdx.y * gridDim.x + blockIdx.x] = r;
    }
}

// ---------------------------------------------------------------------------
// Fused pair kernel: applies conv steps t0 and t0+1.
// grid = (8, 128, 2 + 2*(NB-t0-2)), block = (32, 8).
//   z == 0 : stats for image t0 (single conv of both x & y, no output write)
//   z == 1 : stats for image t0+1 (double conv of both x & y, no output write)
//   z >= 2 : plain double conv of image t0+2+q (x planes then y), write output
// FROM_INPUT (t0==0): sources are the raw 3-channel inputs, summed on load.
// ---------------------------------------------------------------------------
template <bool FROM_INPUT>
__global__ void pair_kernel(const float* __restrict__ xin,
                            const float* __restrict__ yin, int t0) {
    __shared__ float sx[12][136];
    __shared__ float sy[12][136];
    __shared__ float ix[10][136];
    __shared__ float iy[10][136];

    const int p  = t0 >> 1;
    const int wp = p & 1;        // write parity
    const int rp = wp ^ 1;       // read parity (unused for p==0)
    const int nimg = NB - t0;
    const int z = blockIdx.z;
    const int x0 = blockIdx.x * 128;
    const int y0 = blockIdx.y * 8;
    const int tid = threadIdx.y * 32 + threadIdx.x;
    const int ty = threadIdx.y;
    const int cx = threadIdx.x * 4;

    if (z == 0) {
        // ---- stats for image t0: single conv, halo-1 ----
        const float* __restrict__ px;
        const float* __restrict__ py;
        if (FROM_INPUT) {
            px = xin + (size_t)t0 * 3 * NPIX;
            py = yin + (size_t)t0 * 3 * NPIX;
        } else {
            px = g_buf[rp][0] + (size_t)t0 * NPIX;
            py = g_buf[rp][1] + (size_t)t0 * NPIX;
        }
        for (int i = tid; i < 10 * 130; i += 256) {
            int r = i / 130, c = i - r * 130;
            int gy = y0 - 1 + r, gx = x0 - 1 + c;
            float vx = 0.0f, vy = 0.0f;
            if ((unsigned)gy < HH && (unsigned)gx < WW) {
                size_t o = (size_t)gy * WW + gx;
                if (FROM_INPUT) {
                    vx = px[o] + px[o + NPIX] + px[o + 2 * NPIX];
                    vy = py[o] + py[o + NPIX] + py[o + 2 * NPIX];
                } else {
                    vx = px[o];
                    vy = py[o];
                }
            }
            sx[r][c] = vx;
            sy[r][c] = vy;
        }
        __syncthreads();
        float su = 0, su2 = 0, sv = 0, sv2 = 0, suv = 0;
#pragma unroll
        for (int j = 0; j < 4; j++) {
            int cc = cx + 1 + j;
            float ox = c3(sx, ty + 1, cc);
            float oy = c3(sy, ty + 1, cc);
            su += ox; su2 += ox * ox;
            sv += oy; sv2 += oy * oy;
            suv += ox * oy;
        }
        emit_stats(su, su2, sv, sv2, suv, t0);
    } else if (z == 1) {
        // ---- stats for image t0+1: double conv, halo-2 ----
        const int img = t0 + 1;
        const float* __restrict__ px;
        const float* __restrict__ py;
        if (FROM_INPUT) {
            px = xin + (size_t)img * 3 * NPIX;
            py = yin + (size_t)img * 3 * NPIX;
        } else {
            px = g_buf[rp][0] + (size_t)img * NPIX;
            py = g_buf[rp][1] + (size_t)img * NPIX;
        }
        for (int i = tid; i < 12 * 132; i += 256) {
            int r = i / 132, c = i - r * 132;
            int gy = y0 - 2 + r, gx = x0 - 2 + c;
            float vx = 0.0f, vy = 0.0f;
            if ((unsigned)gy < HH && (unsigned)gx < WW) {
                size_t o = (size_t)gy * WW + gx;
                if (FROM_INPUT) {
                    vx = px[o] + px[o + NPIX] + px[o + 2 * NPIX];
                    vy = py[o] + py[o + NPIX] + py[o + 2 * NPIX];
                } else {
                    vx = px[o];
                    vy = py[o];
                }
            }
            sx[r][c] = vx;
            sy[r][c] = vy;
        }
        __syncthreads();
        // intermediate = conv once, MASKED to 0 outside the image
        for (int i = tid; i < 10 * 130; i += 256) {
            int r = i / 130, c = i - r * 130;
            int gy = y0 - 1 + r, gx = x0 - 1 + c;
            bool in = (unsigned)gy < HH && (unsigned)gx < WW;
            ix[r][c] = in ? c3(sx, r + 1, c + 1) : 0.0f;
            iy[r][c] = in ? c3(sy, r + 1, c + 1) : 0.0f;
        }
        __syncthreads();
        float su = 0, su2 = 0, sv = 0, sv2 = 0, suv = 0;
#pragma unroll
        for (int j = 0; j < 4; j++) {
            int cc = cx + 1 + j;
            float ox = c3(ix, ty + 1, cc);
            float oy = c3(iy, ty + 1, cc);
            su += ox; su2 += ox * ox;
            sv += oy; sv2 += oy * oy;
            suv += ox * oy;
        }
        emit_stats(su, su2, sv, sv2, suv, img);
    } else {
        // ---- plain double conv of a future image ----
        int q = z - 2;
        int xy = (q >= nimg - 2) ? 1 : 0;
        int img = t0 + 2 + q - xy * (nimg - 2);
        const float* __restrict__ src;
        if (FROM_INPUT)
            src = (xy ? yin : xin) + (size_t)img * 3 * NPIX;
        else
            src = g_buf[rp][xy] + (size_t)img * NPIX;
        float* __restrict__ dst = g_buf[wp][xy] + (size_t)img * NPIX;

        for (int i = tid; i < 12 * 132; i += 256) {
            int r = i / 132, c = i - r * 132;
            int gy = y0 - 2 + r, gx = x0 - 2 + c;
            float v = 0.0f;
            if ((unsigned)gy < HH && (unsigned)gx < WW) {
                size_t o = (size_t)gy * WW + gx;
                if (FROM_INPUT)
                    v = src[o] + src[o + NPIX] + src[o + 2 * NPIX];
                else
                    v = src[o];
            }
            sx[r][c] = v;
        }
        __syncthreads();
        for (int i = tid; i < 10 * 130; i += 256) {
            int r = i / 130, c = i - r * 130;
            int gy = y0 - 1 + r, gx = x0 - 1 + c;
            bool in = (unsigned)gy < HH && (unsigned)gx < WW;
            ix[r][c] = in ? c3(sx, r + 1, c + 1) : 0.0f;
        }
        __syncthreads();
        float o4[4];
#pragma unroll
        for (int j = 0; j < 4; j++)
            o4[j] = c3(ix, ty + 1, cx + 1 + j);
        *(float4*)(dst + (size_t)(y0 + ty) * WW + x0 + cx) =
            make_float4(o4[0], o4[1], o4[2], o4[3]);
    }
}

// ---------------------------------------------------------------------------
// Tail: reduce partials, compute the 8 SSIM terms in double, sum, write.
// ---------------------------------------------------------------------------
__global__ void final_kernel(float* __restrict__ out) {
    const int w = threadIdx.x >> 5;
    const int lane = threadIdx.x & 31;
    __shared__ double sm[5];
    __shared__ double total_s;
    if (threadIdx.x == 0) total_s = 0.0;

    for (int t = 0; t < NB; t++) {
        if (w < 5) {
            double s = 0.0;
            for (int b = lane; b < NBLK; b += 32)
                s += (double)g_part[t][w][b];
            s = warpSumD(s);
            if (lane == 0) sm[w] = s;
        }
        __syncthreads();
        if (threadIdx.x == 0) {
            double SU = sm[0], SU2 = sm[1], SV = sm[2], SV2 = sm[3], SUV = sm[4];
            double sc = 1.0;
            for (int i = 0; i < t; i++) sc *= 3.0;  // 3^t channel-mixing gain
            const double N = (double)NPIX;
            const double C1 = 6.5025;   // (0.01*255)^2
            const double C2 = 58.5225;  // (0.03*255)^2
            double mu = sc * SU / N;
            double mv = sc * SV / N;
            double varu = sc * sc * (SU2 - SU * SU / N) / (N - 1.0);
            double varv = sc * sc * (SV2 - SV * SV / N) / (N - 1.0);
            double cov  = sc * sc * (SUV - SU * SV / N) / (N - 1.0);
            total_s += ((2.0 * mu * mv + C1) * (2.0 * cov + C2)) /
                       ((mu * mu + mv * mv + C1) * (varu * varu + varv * varv + C2));
        }
        __syncthreads();
    }
    if (threadIdx.x == 0) out[0] = (float)total_s;
}

// ---------------------------------------------------------------------------
extern "C" void kernel_launch(void* const* d_in, const int* in_sizes, int n_in,
                              void* d_out, int out_size) {
    const float* x = (const float*)d_in[0];
    const float* y = (const float*)d_in[1];
    float* out = (float*)d_out;

    for (int p = 0; p < 4; p++) {
        int t0 = 2 * p;
        dim3 grid(WW / 128, HH / 8, 2 + 2 * (NB - t0 - 2));
        dim3 blk(32, 8);
        if (p == 0)
            pair_kernel<true><<<grid, blk>>>(x, y, t0);
        else
            pair_kernel<false><<<grid, blk>>>(x, y, t0);
    }
    final_kernel<<<1, 256>>>(out);
}

// round 6
// speedup vs baseline: 1.8246x; 1.2206x over previous
#include <cuda_runtime.h>

#define HH 1024
#define WW 1024
#define NPIX (HH * WW)
#define NB 8
#define NBLK 512   // (1024/128) x (1024/16) blocks per plane

#define P_ 0.19487471f   // sqrt(0.03797616)
#define Q_ 0.23021729f   // sqrt(0.053)  -> outer([p,q,p],[p,q,p]) == reference 3x3

__device__ float    g_buf[2][2][NB * NPIX];
__device__ float    g_part[NB][5][NBLK];   // [t][moment][block]
__device__ unsigned g_count;

__inline__ __device__ float warpSumF(float v) {
#pragma unroll
    for (int o = 16; o; o >>= 1) v += __shfl_down_sync(0xffffffffu, v, o);
    return v;
}
__inline__ __device__ double warpSumD(double v) {
#pragma unroll
    for (int o = 16; o; o >>= 1) v += __shfl_down_sync(0xffffffffu, v, o);
    return v;
}

// ---------------------------------------------------------------------------
// Halo-2 tile load: A[r][c] <- src(gy = y0-2+r, gx = x0-4+c), zero outside.
// float4-vectorized (x0-4 keeps 16B alignment). Optionally sums 3 channels.
// ---------------------------------------------------------------------------
__device__ __forceinline__ void load_tile(float (*A)[136], const float* __restrict__ src,
                                          int x0, int y0, int tid, bool from_input) {
    for (int i = tid; i < 20 * 34; i += 256) {
        int r = i / 34, c4 = i - r * 34;
        int gy = y0 - 2 + r;
        int gx = x0 - 4 + c4 * 4;
        float4 v = make_float4(0.f, 0.f, 0.f, 0.f);
        if ((unsigned)gy < HH) {
            if (gx >= 0 && gx + 3 < WW) {
                size_t o = (size_t)gy * WW + gx;
                if (from_input) {
                    float4 a = *(const float4*)(src + o);
                    float4 b = *(const float4*)(src + o + NPIX);
                    float4 c = *(const float4*)(src + o + 2 * NPIX);
                    v = make_float4(a.x + b.x + c.x, a.y + b.y + c.y,
                                    a.z + b.z + c.z, a.w + b.w + c.w);
                } else {
                    v = *(const float4*)(src + o);
                }
            } else {
                float t[4] = {0.f, 0.f, 0.f, 0.f};
#pragma unroll
                for (int j = 0; j < 4; j++) {
                    int g = gx + j;
                    if ((unsigned)g < WW) {
                        size_t oo = (size_t)gy * WW + g;
                        t[j] = from_input ? src[oo] + src[oo + NPIX] + src[oo + 2 * NPIX]
                                          : src[oo];
                    }
                }
                v = make_float4(t[0], t[1], t[2], t[3]);
            }
        }
        *(float4*)&A[r][c4 * 4] = v;
    }
}

// ---------------------------------------------------------------------------
// Double separable conv of tile in A (masked between steps); 2x4 outputs/thread.
// out rows gy = y0 + (ty*2+rr), cols gx = x0 + tx*4 + j.
// ---------------------------------------------------------------------------
__device__ __forceinline__ void dconv(float (*A)[136], float (*B)[136],
                                      int x0, int y0, int tid, int tx, int ty,
                                      float o[2][4]) {
    __syncthreads();
    // H1: rows 0..19 (gy=y0-2+r), cols 0..129 (gx=x0-1+c)
    for (int i = tid; i < 20 * 130; i += 256) {
        int r = i / 130, c = i - r * 130;
        B[r][c] = P_ * (A[r][c + 2] + A[r][c + 4]) + Q_ * A[r][c + 3];
    }
    __syncthreads();
    // V1 + in-image mask: rows 0..17 (gy=y0-1+r), cols 0..129 (gx=x0-1+c)
    for (int i = tid; i < 18 * 130; i += 256) {
        int r = i / 130, c = i - r * 130;
        int gy = y0 - 1 + r, gx = x0 - 1 + c;
        float v = P_ * (B[r][c] + B[r + 2][c]) + Q_ * B[r + 1][c];
        A[r][c] = ((unsigned)gy < HH && (unsigned)gx < WW) ? v : 0.0f;
    }
    __syncthreads();
    // H2: rows 0..17, cols 0..127 (gx=x0+c)
    for (int i = tid; i < 18 * 128; i += 256) {
        int r = i >> 7, c = i & 127;
        B[r][c] = P_ * (A[r][c] + A[r][c + 2]) + Q_ * A[r][c + 1];
    }
    __syncthreads();
    // V2 into registers
    const int k = tx * 4;
#pragma unroll
    for (int rr = 0; rr < 2; rr++) {
        int ry = ty * 2 + rr;
        float4 b0 = *(float4*)&B[ry][k];
        float4 b1 = *(float4*)&B[ry + 1][k];
        float4 b2 = *(float4*)&B[ry + 2][k];
        o[rr][0] = P_ * (b0.x + b2.x) + Q_ * b1.x;
        o[rr][1] = P_ * (b0.y + b2.y) + Q_ * b1.y;
        o[rr][2] = P_ * (b0.z + b2.z) + Q_ * b1.z;
        o[rr][3] = P_ * (b0.w + b2.w) + Q_ * b1.w;
    }
}

// Single separable conv (for the z==0 stats plane); same output mapping.
__device__ __forceinline__ void sconv(float (*A)[136], float (*B)[136],
                                      int tid, int tx, int ty, float o[2][4]) {
    __syncthreads();
    for (int i = tid; i < 20 * 130; i += 256) {
        int r = i / 130, c = i - r * 130;
        B[r][c] = P_ * (A[r][c + 2] + A[r][c + 4]) + Q_ * A[r][c + 3];
    }
    __syncthreads();
    const int k = tx * 4;
#pragma unroll
    for (int rr = 0; rr < 2; rr++) {
        int ry = ty * 2 + rr;
#pragma unroll
        for (int j = 0; j < 4; j++)
            o[rr][j] = P_ * (B[ry + 1][k + 1 + j] + B[ry + 3][k + 1 + j])
                     + Q_ * B[ry + 2][k + 1 + j];
    }
}

// ---------------------------------------------------------------------------
// Final reduction + 8 SSIM terms (double), run by the LAST arriving block.
// ---------------------------------------------------------------------------
__device__ void finalize_dev(float* __restrict__ out, int tid) {
    const int w = tid >> 5, lane = tid & 31;
    __shared__ double sm[5];
    __shared__ double tot;
    if (tid == 0) tot = 0.0;
    for (int t = 0; t < NB; t++) {
        if (w < 5) {
            double s = 0.0;
            for (int b = lane; b < NBLK; b += 32) s += (double)g_part[t][w][b];
            s = warpSumD(s);
            if (lane == 0) sm[w] = s;
        }
        __syncthreads();
        if (tid == 0) {
            double SU = sm[0], SU2 = sm[1], SV = sm[2], SV2 = sm[3], SUV = sm[4];
            double sc = 1.0;
            for (int i = 0; i < t; i++) sc *= 3.0;   // 3^t channel-mixing gain
            const double N = (double)NPIX;
            const double C1 = 6.5025;    // (0.01*255)^2
            const double C2 = 58.5225;   // (0.03*255)^2
            double mu = sc * SU / N;
            double mv = sc * SV / N;
            double varu = sc * sc * (SU2 - SU * SU / N) / (N - 1.0);
            double varv = sc * sc * (SV2 - SV * SV / N) / (N - 1.0);
            double cov  = sc * sc * (SUV - SU * SV / N) / (N - 1.0);
            tot += ((2.0 * mu * mv + C1) * (2.0 * cov + C2)) /
                   ((mu * mu + mv * mv + C1) * (varu * varu + varv * varv + C2));
        }
        __syncthreads();
    }
    if (tid == 0) out[0] = (float)tot;
}

// ---------------------------------------------------------------------------
// Pair kernel: conv steps t0 and t0+1. grid=(8,64, 2 + 2*(NB-t0-2)), block=(32,8).
//   z==0: stats image t0 (single conv, x then y, no plane write)
//   z==1: stats image t0+1 (double conv, x then y, no plane write)
//   z>=2: plain double conv of future images, write to ping-pong buffer
// ---------------------------------------------------------------------------
template <bool FROM_INPUT, bool LAST>
__global__ void pair_kernel(const float* __restrict__ xin,
                            const float* __restrict__ yin,
                            int t0, float* __restrict__ out) {
    __shared__ float A[20][136];
    __shared__ float B[20][136];
    const int p  = t0 >> 1;
    const int wp = p & 1;
    const int rp = wp ^ 1;
    const int nimg = NB - t0;
    const int z  = blockIdx.z;
    const int x0 = blockIdx.x * 128;
    const int y0 = blockIdx.y * 16;
    const int tx = threadIdx.x, ty = threadIdx.y;
    const int tid = ty * 32 + tx;

    if (z >= 2) {
        int q = z - 2;
        int xy = (q >= nimg - 2) ? 1 : 0;
        int img = t0 + 2 + q - xy * (nimg - 2);
        const float* src = FROM_INPUT ? ((xy ? yin : xin) + (size_t)img * 3 * NPIX)
                                      : (g_buf[rp][xy] + (size_t)img * NPIX);
        float* dst = g_buf[wp][xy] + (size_t)img * NPIX;
        load_tile(A, src, x0, y0, tid, FROM_INPUT);
        float o[2][4];
        dconv(A, B, x0, y0, tid, tx, ty, o);
#pragma unroll
        for (int rr = 0; rr < 2; rr++) {
            int ry = ty * 2 + rr;
            *(float4*)(dst + (size_t)(y0 + ry) * WW + x0 + tx * 4) =
                make_float4(o[rr][0], o[rr][1], o[rr][2], o[rr][3]);
        }
        return;
    }

    // ---- stats planes ----
    const int t = t0 + z;
    const float* sx = FROM_INPUT ? (xin + (size_t)t * 3 * NPIX)
                                 : (g_buf[rp][0] + (size_t)t * NPIX);
    const float* sy = FROM_INPUT ? (yin + (size_t)t * 3 * NPIX)
                                 : (g_buf[rp][1] + (size_t)t * NPIX);
    float ox[2][4], oy[2][4];
    load_tile(A, sx, x0, y0, tid, FROM_INPUT);
    if (z == 0) sconv(A, B, tid, tx, ty, ox);
    else        dconv(A, B, x0, y0, tid, tx, ty, ox);
    load_tile(A, sy, x0, y0, tid, FROM_INPUT);
    if (z == 0) sconv(A, B, tid, tx, ty, oy);
    else        dconv(A, B, x0, y0, tid, tx, ty, oy);

    float su = 0, su2 = 0, sv = 0, sv2 = 0, suv = 0;
#pragma unroll
    for (int rr = 0; rr < 2; rr++)
#pragma unroll
        for (int j = 0; j < 4; j++) {
            float a = ox[rr][j], b = oy[rr][j];
            su += a; su2 += a * a; sv += b; sv2 += b * b; suv += a * b;
        }
    su = warpSumF(su); su2 = warpSumF(su2); sv = warpSumF(sv);
    sv2 = warpSumF(sv2); suv = warpSumF(suv);

    __shared__ float red[5][8];
    if (tx == 0) {
        red[0][ty] = su; red[1][ty] = su2; red[2][ty] = sv;
        red[3][ty] = sv2; red[4][ty] = suv;
    }
    __syncthreads();
    if (tid < 5) {
        float r = 0.f;
#pragma unroll
        for (int qq = 0; qq < 8; qq++) r += red[tid][qq];
        g_part[t][tid][blockIdx.y * gridDim.x + blockIdx.x] = r;
        if (LAST) __threadfence();
    }

    if (LAST) {
        __shared__ unsigned s_rank;
        __syncthreads();
        if (tid == 0) s_rank = atomicAdd(&g_count, 1u);
        __syncthreads();
        if (s_rank == 2 * NBLK - 1) {     // last of the 1024 blocks
            __threadfence();
            finalize_dev(out, tid);
            if (tid == 0) g_count = 0;    // reset for next graph replay
        }
    }
}

// ---------------------------------------------------------------------------
extern "C" void kernel_launch(void* const* d_in, const int* in_sizes, int n_in,
                              void* d_out, int out_size) {
    const float* x = (const float*)d_in[0];
    const float* y = (const float*)d_in[1];
    float* out = (float*)d_out;
    dim3 blk(32, 8);
    pair_kernel<true,  false><<<dim3(8, 64, 14), blk>>>(x, y, 0, out);
    pair_kernel<false, false><<<dim3(8, 64, 10), blk>>>(x, y, 2, out);
    pair_kernel<false, false><<<dim3(8, 64,  6), blk>>>(x, y, 4, out);
    pair_kernel<false, true ><<<dim3(8, 64,  2), blk>>>(x, y, 6, out);
}

// round 7
// speedup vs baseline: 1.9588x; 1.0736x over previous
#include <cuda_runtime.h>

#define HH 1024
#define WW 1024
#define NPIX (HH * WW)
#define NB 8
#define NBLK 512   // tiles per plane: (1024/128) x (1024/16)

#define P_ 0.19487471f   // sqrt(0.03797616)
#define Q_ 0.23021729f   // sqrt(0.053); outer([p,q,p],[p,q,p]) == reference 3x3

__device__ float    g_buf[2][2][NB * NPIX];
__device__ float    g_part[NB][5][NBLK];
__device__ unsigned g_barcnt;
__device__ volatile unsigned g_sense;

__inline__ __device__ float warpSumF(float v) {
#pragma unroll
    for (int o = 16; o; o >>= 1) v += __shfl_down_sync(0xffffffffu, v, o);
    return v;
}
__inline__ __device__ double warpSumD(double v) {
#pragma unroll
    for (int o = 16; o; o >>= 1) v += __shfl_down_sync(0xffffffffu, v, o);
    return v;
}

// ---- vector conv helpers -------------------------------------------------
__device__ __forceinline__ float4 h1pair(float4 a0, float4 a1) {
    // out col 4k+j reads A cols 4k+2+j .. 4k+4+j
    return make_float4(P_ * (a0.z + a1.x) + Q_ * a0.w,
                       P_ * (a0.w + a1.y) + Q_ * a1.x,
                       P_ * (a1.x + a1.z) + Q_ * a1.y,
                       P_ * (a1.y + a1.w) + Q_ * a1.z);
}
__device__ __forceinline__ float4 h2pair(float4 a0, float4 a1) {
    // out col 4k+j reads A cols 4k+j .. 4k+2+j
    return make_float4(P_ * (a0.x + a0.z) + Q_ * a0.y,
                       P_ * (a0.y + a0.w) + Q_ * a0.z,
                       P_ * (a0.z + a1.x) + Q_ * a0.w,
                       P_ * (a0.w + a1.y) + Q_ * a1.x);
}
__device__ __forceinline__ float4 vpass(float4 a, float4 b, float4 c) {
    return make_float4(P_ * (a.x + c.x) + Q_ * b.x,
                       P_ * (a.y + c.y) + Q_ * b.y,
                       P_ * (a.z + c.z) + Q_ * b.z,
                       P_ * (a.w + c.w) + Q_ * b.w);
}

// ---- halo-2 tile load (float4, zero-padded, optional 3-channel sum) ------
__device__ __forceinline__ void load_tile(float (*A)[136], const float* __restrict__ src,
                                          int x0, int y0, int tid, bool from_input) {
    for (int i = tid; i < 20 * 34; i += 256) {
        int r = i / 34, c4 = i - r * 34;
        int gy = y0 - 2 + r;
        int gx = x0 - 4 + c4 * 4;
        float4 v = make_float4(0.f, 0.f, 0.f, 0.f);
        if ((unsigned)gy < HH) {
            if (gx >= 0 && gx + 3 < WW) {
                size_t o = (size_t)gy * WW + gx;
                if (from_input) {
                    float4 a = *(const float4*)(src + o);
                    float4 b = *(const float4*)(src + o + NPIX);
                    float4 c = *(const float4*)(src + o + 2 * NPIX);
                    v = make_float4(a.x + b.x + c.x, a.y + b.y + c.y,
                                    a.z + b.z + c.z, a.w + b.w + c.w);
                } else {
                    v = *(const float4*)(src + o);
                }
            } else {
                float t[4] = {0.f, 0.f, 0.f, 0.f};
#pragma unroll
                for (int j = 0; j < 4; j++) {
                    int g = gx + j;
                    if ((unsigned)g < WW) {
                        size_t oo = (size_t)gy * WW + g;
                        t[j] = from_input ? src[oo] + src[oo + NPIX] + src[oo + 2 * NPIX]
                                          : src[oo];
                    }
                }
                v = make_float4(t[0], t[1], t[2], t[3]);
            }
        }
        *(float4*)&A[r][c4 * 4] = v;
    }
}

// ---- shared H1 pass: B[r][c] = conv_h at gx = x0-1+c, rows gy=y0-2+r ------
__device__ __forceinline__ void h1_pass(float (*A)[136], float (*B)[136], int tid) {
    __syncthreads();
    for (int i = tid; i < 20 * 33; i += 256) {
        int r = i / 33, k = i - r * 33;
        float4 a0 = *(float4*)&A[r][4 * k];
        float4 a1 = *(float4*)&A[r][4 * k + 4];
        *(float4*)&B[r][4 * k] = h1pair(a0, a1);
    }
    __syncthreads();
}

// ---- double conv (two steps, masked between), 2x4 outputs/thread ---------
__device__ __forceinline__ void dconv(float (*A)[136], float (*B)[136],
                                      int x0, int y0, int tid, float o[2][4]) {
    h1_pass(A, B, tid);
    const bool xlo = (x0 == 0), xhi = (x0 == WW - 128);
    // V1 + in-image mask: A[r][c] is step-1 output at gy=y0-1+r, gx=x0-1+c
    for (int i = tid; i < 18 * 33; i += 256) {
        int r = i / 33, k = i - r * 33;
        float4 b0 = *(float4*)&B[r][4 * k];
        float4 b1 = *(float4*)&B[r + 1][4 * k];
        float4 b2 = *(float4*)&B[r + 2][4 * k];
        float4 v = vpass(b0, b1, b2);
        int gy = y0 - 1 + r;
        if ((unsigned)gy >= HH) v = make_float4(0.f, 0.f, 0.f, 0.f);
        else {
            if (xlo && k == 0) v.x = 0.f;                       // gx = -1
            if (xhi && k == 32) { v.y = 0.f; v.z = 0.f; v.w = 0.f; }  // gx >= 1024
        }
        *(float4*)&A[r][4 * k] = v;
    }
    __syncthreads();
    // H2: B[r][c] at gx = x0+c, gy = y0-1+r
    for (int i = tid; i < 18 * 32; i += 256) {
        int r = i >> 5, k = i & 31;
        float4 a0 = *(float4*)&A[r][4 * k];
        float4 a1 = *(float4*)&A[r][4 * k + 4];
        *(float4*)&B[r][4 * k] = h2pair(a0, a1);
    }
    __syncthreads();
    // V2 into registers: out gy = y0+ty*2+rr, gx = x0+tx*4+j
    const int tx = tid & 31, ty = tid >> 5;
    const int kk = tx * 4;
#pragma unroll
    for (int rr = 0; rr < 2; rr++) {
        int ry = ty * 2 + rr;
        float4 b0 = *(float4*)&B[ry][kk];
        float4 b1 = *(float4*)&B[ry + 1][kk];
        float4 b2 = *(float4*)&B[ry + 2][kk];
        float4 v = vpass(b0, b1, b2);
        o[rr][0] = v.x; o[rr][1] = v.y; o[rr][2] = v.z; o[rr][3] = v.w;
    }
}

// ---- single conv (stats plane 0 of each pair) ----------------------------
__device__ __forceinline__ void sconv(float (*A)[136], float (*B)[136],
                                      int tid, float o[2][4]) {
    h1_pass(A, B, tid);
    // out gy = y0+ty*2+rr (B row ry+1..ry+3), gx = x0+tx*4+j (B col kk+1+j)
    const int tx = tid & 31, ty = tid >> 5;
    const int kk = tx * 4;
#pragma unroll
    for (int rr = 0; rr < 2; rr++) {
        int ry = ty * 2 + rr;
        float4 s[3];
#pragma unroll
        for (int m = 0; m < 3; m++) {
            float4 a0 = *(float4*)&B[ry + 1 + m][kk];
            float4 a1 = *(float4*)&B[ry + 1 + m][kk + 4];
            s[m] = make_float4(a0.y, a0.z, a0.w, a1.x);  // shifted by +1 col
        }
        float4 v = vpass(s[0], s[1], s[2]);
        o[rr][0] = v.x; o[rr][1] = v.y; o[rr][2] = v.z; o[rr][3] = v.w;
    }
}

// ---- global software barrier (sense-reversing, all blocks resident) ------
__device__ __forceinline__ void gbar(int nblocks, unsigned phase, int tid) {
    __syncthreads();
    if (tid == 0) {
        __threadfence();
        unsigned a = atomicAdd(&g_barcnt, 1u);
        if (a == (unsigned)nblocks - 1u) {
            g_barcnt = 0;
            __threadfence();
            g_sense = phase;
        } else {
            while (g_sense < phase) __nanosleep(64);
            __threadfence();
        }
    }
    __syncthreads();
}

// ---- finalize: 8 SSIM terms in double (block 0, 8 warps parallel) --------
__device__ void finalize_dev(float* __restrict__ out, int tid) {
    __shared__ double sm[NB][5];
    const int w = tid >> 5, lane = tid & 31;
    for (int idx = w; idx < NB * 5; idx += 8) {
        int t = idx / 5, m = idx - 5 * t;
        double s = 0.0;
        for (int b = lane; b < NBLK; b += 32) s += (double)g_part[t][m][b];
        s = warpSumD(s);
        if (lane == 0) sm[t][m] = s;
    }
    __syncthreads();
    if (tid == 0) {
        double tot = 0.0, sc = 1.0;
        const double N = (double)NPIX;
        const double C1 = 6.5025;    // (0.01*255)^2
        const double C2 = 58.5225;   // (0.03*255)^2
        for (int t = 0; t < NB; t++) {
            double SU = sm[t][0], SU2 = sm[t][1], SV = sm[t][2],
                   SV2 = sm[t][3], SUV = sm[t][4];
            double mu = sc * SU / N;
            double mv = sc * SV / N;
            double varu = sc * sc * (SU2 - SU * SU / N) / (N - 1.0);
            double varv = sc * sc * (SV2 - SV * SV / N) / (N - 1.0);
            double cov  = sc * sc * (SUV - SU * SV / N) / (N - 1.0);
            tot += ((2.0 * mu * mv + C1) * (2.0 * cov + C2)) /
                   ((mu * mu + mv * mv + C1) * (varu * varu + varv * varv + C2));
            sc *= 3.0;  // 3^t channel-mixing gain
        }
        out[0] = (float)tot;
    }
}

// ---------------------------------------------------------------------------
// Persistent kernel: 4 pair-phases separated by global barriers.
// Pair p (t0=2p) tasks: plane 0/1 = stats images t0, t0+1 (x & y in one task,
// no plane writes); planes 2.. = double conv of future images (write ping-pong).
// ---------------------------------------------------------------------------
__global__ void __launch_bounds__(256, 4)
ssim_persist(const float* __restrict__ xin, const float* __restrict__ yin,
             float* __restrict__ out, int nblocks) {
    __shared__ float A[20][136];
    __shared__ float B[20][136];
    __shared__ float red[5][8];
    const int tid = threadIdx.x;
    const int tx = tid & 31, ty = tid >> 5;

    for (int p = 0; p < 4; p++) {
        const int t0 = 2 * p, nimg = NB - t0;
        const int rp = (p & 1) ^ 1, wp = p & 1;
        const bool fin = (p == 0);
        const int ntasks = (2 + 2 * (nimg - 2)) * NBLK;

        for (int task = blockIdx.x; task < ntasks; task += nblocks) {
            const int plane = task >> 9;
            const int tile = task & 511;
            const int x0 = (tile & 7) * 128;
            const int y0 = (tile >> 3) * 16;

            if (plane >= 2) {
                int q = plane - 2;
                int xy = (q >= nimg - 2) ? 1 : 0;
                int img = t0 + 2 + q - xy * (nimg - 2);
                const float* src = fin ? ((xy ? yin : xin) + (size_t)img * 3 * NPIX)
                                       : (g_buf[rp][xy] + (size_t)img * NPIX);
                float* dst = g_buf[wp][xy] + (size_t)img * NPIX;
                float o[2][4];
                load_tile(A, src, x0, y0, tid, fin);
                dconv(A, B, x0, y0, tid, o);
#pragma unroll
                for (int rr = 0; rr < 2; rr++) {
                    *(float4*)(dst + (size_t)(y0 + ty * 2 + rr) * WW + x0 + tx * 4) =
                        make_float4(o[rr][0], o[rr][1], o[rr][2], o[rr][3]);
                }
            } else {
                const int t = t0 + plane;
                const float* sx = fin ? (xin + (size_t)t * 3 * NPIX)
                                      : (g_buf[rp][0] + (size_t)t * NPIX);
                const float* sy = fin ? (yin + (size_t)t * 3 * NPIX)
                                      : (g_buf[rp][1] + (size_t)t * NPIX);
                float ox[2][4], oy[2][4];
                load_tile(A, sx, x0, y0, tid, fin);
                if (plane == 0) sconv(A, B, tid, ox);
                else            dconv(A, B, x0, y0, tid, ox);
                load_tile(A, sy, x0, y0, tid, fin);
                if (plane == 0) sconv(A, B, tid, oy);
                else            dconv(A, B, x0, y0, tid, oy);

                float su = 0, su2 = 0, sv = 0, sv2 = 0, suv = 0;
#pragma unroll
                for (int rr = 0; rr < 2; rr++)
#pragma unroll
                    for (int j = 0; j < 4; j++) {
                        float a = ox[rr][j], b = oy[rr][j];
                        su += a; su2 += a * a; sv += b; sv2 += b * b; suv += a * b;
                    }
                su = warpSumF(su); su2 = warpSumF(su2); sv = warpSumF(sv);
                sv2 = warpSumF(sv2); suv = warpSumF(suv);
                if (tx == 0) {
                    red[0][ty] = su; red[1][ty] = su2; red[2][ty] = sv;
                    red[3][ty] = sv2; red[4][ty] = suv;
                }
                __syncthreads();
                if (tid < 5) {
                    float r = 0.f;
#pragma unroll
                    for (int qq = 0; qq < 8; qq++) r += red[tid][qq];
                    g_part[t][tid][tile] = r;
                }
                __syncthreads();
            }
        }
        gbar(nblocks, (unsigned)(p + 1), tid);
    }

    if (blockIdx.x == 0) {
        finalize_dev(out, tid);
        if (tid == 0) {
            __threadfence();
            g_sense = 0;  // reset for next graph replay
        }
    }
}

// ---------------------------------------------------------------------------
extern "C" void kernel_launch(void* const* d_in, const int* in_sizes, int n_in,
                              void* d_out, int out_size) {
    const float* x = (const float*)d_in[0];
    const float* y = (const float*)d_in[1];
    float* out = (float*)d_out;

    int dev = 0;
    cudaGetDevice(&dev);
    int sms = 148;
    cudaDeviceGetAttribute(&sms, cudaDevAttrMultiProcessorCount, dev);
    int occ = 1;
    cudaOccupancyMaxActiveBlocksPerMultiprocessor(&occ, ssim_persist, 256, 0);
    if (occ < 1) occ = 1;
    int nblocks = sms * occ;

    ssim_persist<<<nblocks, 256>>>(x, y, out, nblocks);
}